// round 3
// baseline (speedup 1.0000x reference)
#include <cuda_runtime.h>

// ---------------------------------------------------------------------------
// MoE Router: logits = X[16384,2048] @ W[64,2048]^T + b ; softmax; top-2;
// renormalized weights; one-hot mask.
// Output (fp32, flattened tuple):
//   [0, 1048576)            router_logits  [T,64]
//   [1048576, 1081344)      router_weights [T,2]
//   [1081344, 1114112)      selected_experts [T,2] (as float)
//   [1114112, 3211264)      expert_mask [T,2,64] (as float 0/1)
// ---------------------------------------------------------------------------

#define T_TOKENS 16384
#define K_DIM    2048
#define E_DIM    64
#define BLK_T    128
#define KC       16
#define NCHUNK   (K_DIM / KC)

#define OFF_W    (T_TOKENS * E_DIM)            // 1048576
#define OFF_SEL  (OFF_W + T_TOKENS * 2)        // 1081344
#define OFF_MASK (OFF_SEL + T_TOKENS * 2)      // 1114112

// Packed dual-fp32 FMA (Blackwell FFMA2): d.lo = a.lo*b.lo+c.lo, d.hi likewise.
__device__ __forceinline__ unsigned long long ffma2(unsigned long long a,
                                                    unsigned long long b,
                                                    unsigned long long c) {
    unsigned long long d;
    asm("fma.rn.f32x2 %0, %1, %2, %3;" : "=l"(d) : "l"(a), "l"(b), "l"(c));
    return d;
}

__global__ __launch_bounds__(256, 1)
void moe_gemm_kernel(const float* __restrict__ X,
                     const float* __restrict__ W,
                     const float* __restrict__ b,
                     float* __restrict__ out)
{
    // Xs[buf][k][token]  (transposed so adjacent tokens are contiguous -> f32x2)
    // stride 130 keeps 8B alignment for even tokens and conflict-free STS.
    __shared__ __align__(16) float  Xs[2][KC][130];
    // Wd[buf][k][expert] = {w, w} duplicated pair for packed FMA broadcast.
    __shared__ __align__(16) float2 Wd[2][KC][66];

    const int tid = threadIdx.x;
    const int t0  = blockIdx.x * BLK_T;

    const int tx = tid & 15;   // expert lane: experts tx + 16*i
    const int ty = tid >> 4;   // token row group: pairs p = ty + 16*j

    // -------- global load pointers (each thread: 2 X float4 + 1 W float4/chunk)
    const int ta = tid >> 2;           // token slot 0..63
    const int tb = (tid + 256) >> 2;   // token slot 64..127
    const int kq = tid & 3;            // float4 index within 16-float chunk

    const float4* xg0 = (const float4*)X + (size_t)(t0 + ta) * (K_DIM / 4) + kq;
    const float4* xg1 = (const float4*)X + (size_t)(t0 + tb) * (K_DIM / 4) + kq;
    const float4* wg  = (const float4*)W + (size_t)ta * (K_DIM / 4) + kq;

    unsigned long long acc[4][4];
#pragma unroll
    for (int j = 0; j < 4; ++j)
#pragma unroll
        for (int i = 0; i < 4; ++i) acc[j][i] = 0ULL;

#define STAGE(BUF, VA, VB, VW) do {                                          \
        int kk = kq * 4;                                                     \
        Xs[BUF][kk + 0][ta] = (VA).x;  Xs[BUF][kk + 1][ta] = (VA).y;         \
        Xs[BUF][kk + 2][ta] = (VA).z;  Xs[BUF][kk + 3][ta] = (VA).w;         \
        Xs[BUF][kk + 0][tb] = (VB).x;  Xs[BUF][kk + 1][tb] = (VB).y;         \
        Xs[BUF][kk + 2][tb] = (VB).z;  Xs[BUF][kk + 3][tb] = (VB).w;         \
        Wd[BUF][kk + 0][ta] = make_float2((VW).x, (VW).x);                   \
        Wd[BUF][kk + 1][ta] = make_float2((VW).y, (VW).y);                   \
        Wd[BUF][kk + 2][ta] = make_float2((VW).z, (VW).z);                   \
        Wd[BUF][kk + 3][ta] = make_float2((VW).w, (VW).w);                   \
    } while (0)

    // prologue: chunk 0
    float4 ra = xg0[0];
    float4 rb = xg1[0];
    float4 rw = wg[0];
    STAGE(0, ra, rb, rw);
    __syncthreads();

    for (int c = 0; c < NCHUNK; ++c) {
        const int buf = c & 1;
        if (c + 1 < NCHUNK) {
            ra = xg0[(c + 1) * 4];
            rb = xg1[(c + 1) * 4];
            rw = wg[(c + 1) * 4];
        }
#pragma unroll
        for (int k = 0; k < KC; ++k) {
            unsigned long long xp[4], wp[4];
#pragma unroll
            for (int j = 0; j < 4; ++j)
                xp[j] = *(const unsigned long long*)&Xs[buf][k][2 * (ty + 16 * j)];
#pragma unroll
            for (int i = 0; i < 4; ++i)
                wp[i] = *(const unsigned long long*)&Wd[buf][k][tx + 16 * i];
#pragma unroll
            for (int j = 0; j < 4; ++j)
#pragma unroll
                for (int i = 0; i < 4; ++i)
                    acc[j][i] = ffma2(xp[j], wp[i], acc[j][i]);
        }
        if (c + 1 < NCHUNK) {
            STAGE((c + 1) & 1, ra, rb, rw);
            __syncthreads();
        }
    }
#undef STAGE

    // epilogue: add bias, write logits
    float bias[4];
#pragma unroll
    for (int i = 0; i < 4; ++i) bias[i] = __ldg(&b[tx + 16 * i]);

#pragma unroll
    for (int j = 0; j < 4; ++j) {
        const int tok = t0 + 2 * (ty + 16 * j);
#pragma unroll
        for (int i = 0; i < 4; ++i) {
            const int e = tx + 16 * i;
            const float lo = __uint_as_float((unsigned)(acc[j][i] & 0xffffffffULL));
            const float hi = __uint_as_float((unsigned)(acc[j][i] >> 32));
            out[(size_t)tok * E_DIM + e]       = lo + bias[i];
            out[(size_t)(tok + 1) * E_DIM + e] = hi + bias[i];
        }
    }
}

// ---------------------------------------------------------------------------
// Softmax + top-2 + renorm + one-hot, one warp per token.
// Tie semantics match jax.lax.top_k: equal values -> lower index first.
// ---------------------------------------------------------------------------
__global__ __launch_bounds__(256)
void moe_router_kernel(float* __restrict__ out)
{
    const int warp = threadIdx.x >> 5;
    const int lane = threadIdx.x & 31;
    const int t = blockIdx.x * 8 + warp;

    const float* lrow = out + (size_t)t * E_DIM;
    const float2 lv = *(const float2*)(lrow + 2 * lane);   // experts 2*lane, 2*lane+1

    float m = fmaxf(lv.x, lv.y);
#pragma unroll
    for (int o = 16; o; o >>= 1) m = fmaxf(m, __shfl_xor_sync(0xffffffffu, m, o));

    const float p0 = expf(lv.x - m);
    const float p1 = expf(lv.y - m);
    float s = p0 + p1;
#pragma unroll
    for (int o = 16; o; o >>= 1) s += __shfl_xor_sync(0xffffffffu, s, o);

    const float pr0 = p0 / s;
    const float pr1 = p1 / s;

    float a1, a2;
    int   i1, i2;
    if (pr0 >= pr1) { a1 = pr0; i1 = 2 * lane;     a2 = pr1; i2 = 2 * lane + 1; }
    else            { a1 = pr1; i1 = 2 * lane + 1; a2 = pr0; i2 = 2 * lane;     }

#pragma unroll
    for (int o = 16; o; o >>= 1) {
        const float b1 = __shfl_xor_sync(0xffffffffu, a1, o);
        const int   j1 = __shfl_xor_sync(0xffffffffu, i1, o);
        const float b2 = __shfl_xor_sync(0xffffffffu, a2, o);
        const int   j2 = __shfl_xor_sync(0xffffffffu, i2, o);
        const bool firstA = (a1 > b1) || (a1 == b1 && i1 < j1);
        float n1, n2; int ni1, ni2;
        if (firstA) {
            n1 = a1; ni1 = i1;
            const bool sA = (a2 > b1) || (a2 == b1 && i2 < j1);
            n2 = sA ? a2 : b1; ni2 = sA ? i2 : j1;
        } else {
            n1 = b1; ni1 = j1;
            const bool sB = (a1 > b2) || (a1 == b2 && i1 < j2);
            n2 = sB ? a1 : b2; ni2 = sB ? i1 : j2;
        }
        a1 = n1; i1 = ni1; a2 = n2; i2 = ni2;
    }

    const float denom = a1 + a2;
    if (lane == 0) {
        out[OFF_W + 2 * t]     = a1 / denom;
        out[OFF_W + 2 * t + 1] = a2 / denom;
        out[OFF_SEL + 2 * t]     = (float)i1;
        out[OFF_SEL + 2 * t + 1] = (float)i2;
    }

    float2 m0, m1v;
    m0.x  = (2 * lane     == i1) ? 1.f : 0.f;
    m0.y  = (2 * lane + 1 == i1) ? 1.f : 0.f;
    m1v.x = (2 * lane     == i2) ? 1.f : 0.f;
    m1v.y = (2 * lane + 1 == i2) ? 1.f : 0.f;
    *(float2*)(out + OFF_MASK + (size_t)t * 128 + 2 * lane)      = m0;
    *(float2*)(out + OFF_MASK + (size_t)t * 128 + 64 + 2 * lane) = m1v;
}

extern "C" void kernel_launch(void* const* d_in, const int* in_sizes, int n_in,
                              void* d_out, int out_size)
{
    const float* X = (const float*)d_in[0];
    const float* W = (const float*)d_in[1];
    const float* b = (const float*)d_in[2];
    float* out = (float*)d_out;

    moe_gemm_kernel<<<T_TOKENS / BLK_T, 256>>>(X, W, b, out);
    moe_router_kernel<<<T_TOKENS / 8, 256>>>(out);
}

// round 6
// speedup vs baseline: 1.1928x; 1.1928x over previous
#include <cuda_runtime.h>
#include <math.h>

// ---------------------------------------------------------------------------
// MoE Router via 3xTF32 mma.sync GEMM (chunked accumulators to kill HMMA
// truncation bias) + fused softmax/top-2 epilogue.
// logits = X[16384,2048] @ W[64,2048]^T + b ; softmax; top-2; renorm; one-hot.
// Output (fp32 flattened): logits | weights | selected(as float) | mask
// ---------------------------------------------------------------------------

#define T_TOKENS 16384
#define K_DIM    2048
#define E_DIM    64
#define BLK_T    128
#define KC       32                 // K elements per chunk
#define NCHUNK   (K_DIM / KC)       // 64

#define OFF_W    (T_TOKENS * E_DIM)
#define OFF_SEL  (OFF_W + T_TOKENS * 2)
#define OFF_MASK (OFF_SEL + T_TOKENS * 2)

// SMEM layout (bytes). A tile: 128 rows x 32 k as float2(hi,lo) = 32KB.
// B tile: 64 rows x 32 k as float2 = 16KB. Double buffered.
#define ABUF0 0
#define ABUF1 32768
#define BBUF0 65536
#define BBUF1 81920
#define SBIAS 98304
#define SMEM_TOTAL (98304 + 256)
// logits scratch aliases ABUF after the mainloop: 128 x 65 fp32 = 33,280B

static __device__ float2 g_Wsplit[E_DIM * K_DIM];   // (hi, lo) tf32 pairs

__device__ __forceinline__ float tf32r(float x) {
    unsigned u;
    asm("cvt.rna.tf32.f32 %0, %1;" : "=r"(u) : "f"(x));
    return __uint_as_float(u);
}

__device__ __forceinline__ void mma8(float* c, const unsigned* a, const unsigned* b) {
    asm("mma.sync.aligned.m16n8k8.row.col.f32.tf32.tf32.f32 "
        "{%0,%1,%2,%3}, {%4,%5,%6,%7}, {%8,%9}, {%0,%1,%2,%3};"
        : "+f"(c[0]), "+f"(c[1]), "+f"(c[2]), "+f"(c[3])
        : "r"(a[0]), "r"(a[1]), "r"(a[2]), "r"(a[3]), "r"(b[0]), "r"(b[1]));
}
// C = A*B (fresh accumulator -> bounds coherent HMMA rounding to chunk scope)
__device__ __forceinline__ void mma8z(float* c, const unsigned* a, const unsigned* b) {
    asm("mma.sync.aligned.m16n8k8.row.col.f32.tf32.tf32.f32 "
        "{%0,%1,%2,%3}, {%4,%5,%6,%7}, {%8,%9}, {%10,%10,%10,%10};"
        : "=f"(c[0]), "=f"(c[1]), "=f"(c[2]), "=f"(c[3])
        : "r"(a[0]), "r"(a[1]), "r"(a[2]), "r"(a[3]), "r"(b[0]), "r"(b[1]),
          "f"(0.0f));
}

// ---------------- W split pre-kernel ----------------
__global__ void wsplit_kernel(const float* __restrict__ W) {
    int i = blockIdx.x * 256 + threadIdx.x;
    float w = W[i];
    float hi = tf32r(w);
    g_Wsplit[i] = make_float2(hi, tf32r(w - hi));
}

// ---------------- main kernel ----------------
__global__ __launch_bounds__(256, 1)
void moe_mma_kernel(const float* __restrict__ X,
                    const float* __restrict__ bias,
                    float* __restrict__ out)
{
    extern __shared__ char sm[];
    const int tid  = threadIdx.x;
    const int wid  = tid >> 5;
    const int lane = tid & 31;
    const int t0   = blockIdx.x * BLK_T;

    const int g  = lane >> 2;        // group id 0..7
    const int tg = lane & 3;         // thread-in-group
    const int sw = g << 2;           // smem XOR swizzle for this thread
    const int RB = (wid >> 1) * 32;  // warp row base (tokens)
    const int CB = (wid & 1) * 32;   // warp col base (experts)

    if (tid < E_DIM) ((float*)(sm + SBIAS))[tid] = bias[tid];

    const float4* X4 = (const float4*)X;
    const float4* W4 = (const float4*)g_Wsplit;   // 1024 float4 per expert row

    float acc[2][4][4];              // running fp32 (RN) accumulator
#pragma unroll
    for (int mi = 0; mi < 2; ++mi)
#pragma unroll
        for (int ni = 0; ni < 4; ++ni)
#pragma unroll
            for (int q = 0; q < 4; ++q) acc[mi][ni][q] = 0.f;

    float4 xr[4], wr[4];

    // ---- staging helpers ----
#define LDGX(C) do {                                                          \
    _Pragma("unroll")                                                         \
    for (int q = 0; q < 4; ++q) {                                             \
        int e = tid + (q << 8);                                               \
        xr[q] = X4[(size_t)(t0 + (e >> 3)) * (K_DIM / 4) + (C) * 8 + (e & 7)];\
    } } while (0)

#define LDGW(C) do {                                                          \
    _Pragma("unroll")                                                         \
    for (int q = 0; q < 4; ++q) {                                             \
        int e = tid + (q << 8);                                               \
        wr[q] = W4[(size_t)(e >> 4) * (K_DIM / 2) + (C) * 16 + (e & 15)];     \
    } } while (0)

#define STAGE(P) do {                                                         \
    char* ab = sm + ((P) ? ABUF1 : ABUF0);                                    \
    char* bb = sm + ((P) ? BBUF1 : BBUF0);                                    \
    _Pragma("unroll")                                                         \
    for (int q = 0; q < 4; ++q) {                                             \
        int e = tid + (q << 8);                                               \
        int row = e >> 3, j = e & 7, ss = (row & 7) << 2;                     \
        float4 v = xr[q];                                                     \
        float h0 = tf32r(v.x), h1 = tf32r(v.y), h2 = tf32r(v.z), h3 = tf32r(v.w); \
        float l0 = tf32r(v.x - h0), l1 = tf32r(v.y - h1);                     \
        float l2 = tf32r(v.z - h2), l3 = tf32r(v.w - h3);                     \
        *(float4*)(ab + (size_t)(row * 32 + ((4 * j) ^ ss)) * 8)              \
            = make_float4(h0, l0, h1, l1);                                    \
        *(float4*)(ab + (size_t)(row * 32 + ((4 * j + 2) ^ ss)) * 8)          \
            = make_float4(h2, l2, h3, l3);                                    \
    }                                                                         \
    _Pragma("unroll")                                                         \
    for (int q = 0; q < 4; ++q) {                                             \
        int e = tid + (q << 8);                                               \
        int row = e >> 4, j = e & 15, ss = (row & 7) << 2;                    \
        *(float4*)(bb + (size_t)(row * 32 + ((2 * j) ^ ss)) * 8) = wr[q];     \
    } } while (0)

    // prologue: stage chunk 0, prefetch chunk 1
    LDGX(0); LDGW(0);
    STAGE(0);
    LDGX(1); LDGW(1);
    __syncthreads();

    for (int c = 0; c < NCHUNK; ++c) {
        const int p = c & 1;
        if (c + 1 < NCHUNK) {
            STAGE(p ^ 1);                       // chunk c+1 from regs
            if (c + 2 < NCHUNK) { LDGX(c + 2); LDGW(c + 2); }
        }
        // ---- compute chunk c from buffer p into fresh chunk accumulators ----
        const float2* Ab = (const float2*)(sm + (p ? ABUF1 : ABUF0));
        const float2* Bb = (const float2*)(sm + (p ? BBUF1 : BBUF0));
        float cacc[2][4][4];
#pragma unroll
        for (int kk = 0; kk < KC; kk += 8) {
            unsigned ah[2][4], al[2][4], bh[4][2], bl[4][2];
#pragma unroll
            for (int mi = 0; mi < 2; ++mi) {
                const int rb = RB + 16 * mi + g;
#pragma unroll
                for (int idx = 0; idx < 4; ++idx) {
                    const int r = rb + (idx & 1) * 8;
                    const int cc = kk + tg + (idx >> 1) * 4;
                    float2 v = Ab[r * 32 + (cc ^ sw)];
                    ah[mi][idx] = __float_as_uint(v.x);
                    al[mi][idx] = __float_as_uint(v.y);
                }
            }
#pragma unroll
            for (int ni = 0; ni < 4; ++ni) {
                const int rb = CB + 8 * ni + g;
#pragma unroll
                for (int bx = 0; bx < 2; ++bx) {
                    const int cc = kk + tg + 4 * bx;
                    float2 v = Bb[rb * 32 + (cc ^ sw)];
                    bh[ni][bx] = __float_as_uint(v.x);
                    bl[ni][bx] = __float_as_uint(v.y);
                }
            }
#pragma unroll
            for (int mi = 0; mi < 2; ++mi)
#pragma unroll
                for (int ni = 0; ni < 4; ++ni) {
                    if (kk == 0) mma8z(cacc[mi][ni], ah[mi], bh[ni]);
                    else         mma8 (cacc[mi][ni], ah[mi], bh[ni]);
                    mma8(cacc[mi][ni], ah[mi], bl[ni]);
                    mma8(cacc[mi][ni], al[mi], bh[ni]);
                }
        }
        // fold chunk partials into running fp32 accumulator (RN adds)
#pragma unroll
        for (int mi = 0; mi < 2; ++mi)
#pragma unroll
            for (int ni = 0; ni < 4; ++ni)
#pragma unroll
                for (int q = 0; q < 4; ++q)
                    acc[mi][ni][q] += cacc[mi][ni][q];
        __syncthreads();
    }

    // ---------------- epilogue: logits to gmem + smem ----------------
    float* lsm = (float*)sm;                 // 128 x 65 fp32 (aliases A bufs)
    const float* bs = (const float*)(sm + SBIAS);

#pragma unroll
    for (int mi = 0; mi < 2; ++mi) {
        const int r0 = RB + 16 * mi + g;
#pragma unroll
        for (int ni = 0; ni < 4; ++ni) {
            const int col = CB + 8 * ni + 2 * tg;
            const float b0 = bs[col], b1 = bs[col + 1];
            const float v00 = acc[mi][ni][0] + b0, v01 = acc[mi][ni][1] + b1;
            const float v10 = acc[mi][ni][2] + b0, v11 = acc[mi][ni][3] + b1;
            *(float2*)(out + (size_t)(t0 + r0) * E_DIM + col)     = make_float2(v00, v01);
            *(float2*)(out + (size_t)(t0 + r0 + 8) * E_DIM + col) = make_float2(v10, v11);
            lsm[r0 * 65 + col]           = v00;
            lsm[r0 * 65 + col + 1]       = v01;
            lsm[(r0 + 8) * 65 + col]     = v10;
            lsm[(r0 + 8) * 65 + col + 1] = v11;
        }
    }
    __syncthreads();

    // ---------------- fused router: one thread per token ----------------
    if (tid < BLK_T) {
        const int tok = t0 + tid;
        const float* row = lsm + tid * 65;
        float b1 = -1e30f, b2 = -1e30f;
        int   i1 = 0,      i2 = 0;
#pragma unroll
        for (int e = 0; e < E_DIM; ++e) {
            const float v = row[e];
            if (v > b1)      { b2 = b1; i2 = i1; b1 = v; i1 = e; }
            else if (v > b2) { b2 = v; i2 = e; }
        }
        const float e2 = expf(b2 - b1);        // softmax denom cancels in renorm
        const float w1 = 1.0f / (1.0f + e2);
        out[OFF_W + 2 * tok]     = w1;
        out[OFF_W + 2 * tok + 1] = e2 * w1;
        out[OFF_SEL + 2 * tok]     = (float)i1;
        out[OFF_SEL + 2 * tok + 1] = (float)i2;

        float4* m4 = (float4*)(out + OFF_MASK + (size_t)tok * 128);
        const float4 z = make_float4(0.f, 0.f, 0.f, 0.f);
#pragma unroll
        for (int q = 0; q < 32; ++q) m4[q] = z;
        out[OFF_MASK + (size_t)tok * 128 + i1]      = 1.0f;
        out[OFF_MASK + (size_t)tok * 128 + 64 + i2] = 1.0f;
    }
}

extern "C" void kernel_launch(void* const* d_in, const int* in_sizes, int n_in,
                              void* d_out, int out_size)
{
    const float* X = (const float*)d_in[0];
    const float* W = (const float*)d_in[1];
    const float* b = (const float*)d_in[2];
    float* out = (float*)d_out;

    cudaFuncSetAttribute(moe_mma_kernel,
                         cudaFuncAttributeMaxDynamicSharedMemorySize, SMEM_TOTAL);

    wsplit_kernel<<<(E_DIM * K_DIM) / 256, 256>>>(W);
    moe_mma_kernel<<<T_TOKENS / BLK_T, 256, SMEM_TOTAL>>>(X, b, out);
}